// round 7
// baseline (speedup 1.0000x reference)
#include <cuda_runtime.h>
#include <cstdint>

// TrajectoryScore: 64 segments x 100000 obs. HBM-streaming reduction.
// out[0:64)=log_like, out[64:128)=hits, out[128:192)=hits_raw(==hits).
//
// R6: R5 + fractional L2 pinning of u_obs. u_pred (76.8MB) evict_last (all);
// u_obs 50% evict_last / 50% evict_first (~38MB resident). Total pinned
// ~115MB < 126MB L2. Steady-state DRAM traffic per replay ~40MB.

#define SEGS        64
#define SPS         100                 // stages per segment
#define NSTAGE      (SEGS * SPS)        // 6400
#define STAGE_BYTES 12000               // per tensor (1000 rows), 16B multiple
#define GROUPS      250                 // 4-row groups per stage
#define THREADS     256
#define NBLK        296                 // 148 SMs * 2 CTAs
#define QW          (NSTAGE / NBLK)     // 21
#define RW          (NSTAGE - NBLK * QW)// 184
#define NSTG        4                   // pipeline depth
#define BUF_BYTES   (2 * STAGE_BYTES)   // pred + obs per stage (24000)
#define MBAR_OFF    (NSTG * BUF_BYTES)  // 96000
#define SMEM_TOTAL  (MBAR_OFF + 2 * NSTG * 8)

__device__ float        g_acc[2 * SEGS];   // zero-init at module load
__device__ unsigned int g_done;

__device__ __forceinline__ uint32_t smem_u32(const void* p) {
    uint32_t r;
    asm("{ .reg .u64 t; cvta.to.shared.u64 t, %1; cvt.u32.u64 %0, t; }"
        : "=r"(r) : "l"(p));
    return r;
}
__device__ __forceinline__ void mbar_init(uint32_t a, uint32_t cnt) {
    asm volatile("mbarrier.init.shared.b64 [%0], %1;" :: "r"(a), "r"(cnt) : "memory");
}
__device__ __forceinline__ void mbar_arrive(uint32_t a) {
    asm volatile("mbarrier.arrive.shared.b64 _, [%0];" :: "r"(a) : "memory");
}
__device__ __forceinline__ void mbar_expect_tx(uint32_t a, uint32_t bytes) {
    asm volatile("mbarrier.arrive.expect_tx.shared.b64 _, [%0], %1;"
                 :: "r"(a), "r"(bytes) : "memory");
}
__device__ __forceinline__ void mbar_wait(uint32_t a, uint32_t phase) {
    asm volatile(
        "{\n\t.reg .pred P;\n\t"
        "W%=:\n\t"
        "mbarrier.try_wait.parity.acquire.cta.shared::cta.b64 P, [%0], %1, 0x989680;\n\t"
        "@P bra D%=;\n\t"
        "bra W%=;\n\t"
        "D%=:\n\t}"
        :: "r"(a), "r"(phase) : "memory");
}
// TMA bulk load with explicit L2 eviction policy
__device__ __forceinline__ void bulk_ld_pol(uint32_t smem_dst, const void* gsrc,
                                            uint32_t bytes, uint32_t mbar,
                                            uint64_t pol) {
    asm volatile(
        "cp.async.bulk.shared::cta.global.mbarrier::complete_tx::bytes.L2::cache_hint "
        "[%0], [%1], %2, [%3], %4;"
        :: "r"(smem_dst), "l"(gsrc), "r"(bytes), "r"(mbar), "l"(pol) : "memory");
}
__device__ __forceinline__ uint64_t pol_evict_last() {
    uint64_t p;
    asm("createpolicy.fractional.L2::evict_last.b64 %0, 1.0;" : "=l"(p));
    return p;
}
// 50% evict_last / 50% evict_first for the u_obs stream
__device__ __forceinline__ uint64_t pol_half_last() {
    uint64_t p;
    asm("createpolicy.fractional.L2::evict_last.L2::evict_first.b64 %0, 0.5;" : "=l"(p));
    return p;
}

__global__ __launch_bounds__(THREADS, 2)
void trajectory_score_kernel(const float* __restrict__ u_pred,
                             const float* __restrict__ u_obs,
                             const float* __restrict__ h,
                             const float* __restrict__ lam,
                             const float* __restrict__ thresh,
                             float* __restrict__ out) {
    extern __shared__ char dsm[];
    const int b   = blockIdx.x;
    const int tid = threadIdx.x;

    const uint32_t smem_base = smem_u32(dsm);
    const uint32_t mb        = smem_base + MBAR_OFF;   // full[i]@+16i, empty@+16i+8

    __shared__ float    sl[THREADS / 32];
    __shared__ float    sh[THREADS / 32];
    __shared__ unsigned s_ticket;

    const int s0   = b * QW + min(b, RW);
    const int nloc = QW + (b < RW ? 1 : 0);

    const char* gp = (const char*)u_pred;
    const char* go = (const char*)u_obs;

    if (tid == 0) {
#pragma unroll
        for (int i = 0; i < NSTG; ++i) {
            mbar_init(mb + 16 * i, 1);           // full
            mbar_init(mb + 16 * i + 8, THREADS); // empty
        }
    }
    __syncthreads();

    const uint64_t POL_P = pol_evict_last();     // u_pred: fully pinned
    const uint64_t POL_O = pol_half_last();      // u_obs: ~50% pinned

    if (tid == 0) {
        asm volatile("fence.proxy.async.shared::cta;" ::: "memory");
        const int pre = min(NSTG, nloc);
        for (int j = 0; j < pre; ++j) {
            const size_t off  = (size_t)(s0 + j) * STAGE_BYTES;
            const uint32_t bo = smem_base + j * BUF_BYTES;
            mbar_expect_tx(mb + 16 * j, 2 * STAGE_BYTES);
            bulk_ld_pol(bo,               gp + off, STAGE_BYTES, mb + 16 * j, POL_P);
            bulk_ld_pol(bo + STAGE_BYTES, go + off, STAGE_BYTES, mb + 16 * j, POL_O);
        }
    }

    const int lane = tid & 31;
    const int wid  = tid >> 5;

    float slog = 0.0f, shit = 0.0f;
    int   cur_seg = s0 / SPS;

    float hs  = __ldg(h + cur_seg);
    float ls  = __ldg(lam + cur_seg);
    float ts  = __ldg(thresh + cur_seg);
    float c   = hs * ls * __frcp_rn(1.0f - __expf(-ls));
    float omh = 1.0f - hs;
    float nli = -ls * __frcp_rn(ts);
    float t19 = 19.0f * omh;

    for (int i = 0; i < nloc; ++i) {
        const int gs  = s0 + i;
        const int seg = gs / SPS;
        if (seg != cur_seg) {
#pragma unroll
            for (int off = 16; off > 0; off >>= 1) {
                slog += __shfl_down_sync(0xFFFFFFFFu, slog, off);
                shit += __shfl_down_sync(0xFFFFFFFFu, shit, off);
            }
            if (lane == 0) { sl[wid] = slog; sh[wid] = shit; }
            __syncthreads();
            if (tid == 0) {
                float ta = 0.0f, tb = 0.0f;
#pragma unroll
                for (int w = 0; w < THREADS / 32; ++w) { ta += sl[w]; tb += sh[w]; }
                atomicAdd(&g_acc[cur_seg], ta);
                atomicAdd(&g_acc[SEGS + cur_seg], tb);
            }
            __syncthreads();
            slog = 0.0f; shit = 0.0f;
            cur_seg = seg;
            hs  = __ldg(h + seg);
            ls  = __ldg(lam + seg);
            ts  = __ldg(thresh + seg);
            c   = hs * ls * __frcp_rn(1.0f - __expf(-ls));
            omh = 1.0f - hs;
            nli = -ls * __frcp_rn(ts);
            t19 = 19.0f * omh;
        }

        const int      si = i & (NSTG - 1);
        const uint32_t ph = (i >> 2) & 1;
        mbar_wait(mb + 16 * si, ph);           // wait full

        if (tid < GROUPS) {
            const char* pb = dsm + si * BUF_BYTES + 48 * tid;
            const float4 va = *(const float4*)(pb + 0);
            const float4 vb = *(const float4*)(pb + 16);
            const float4 vc = *(const float4*)(pb + 32);
            const float4 wa = *(const float4*)(pb + STAGE_BYTES + 0);
            const float4 wb = *(const float4*)(pb + STAGE_BYTES + 16);
            const float4 wc = *(const float4*)(pb + STAGE_BYTES + 32);

            float s2[4];
            {
                float dx = va.x - wa.x, dy = va.y - wa.y, dz = va.z - wa.z;
                s2[0] = dx * dx + dy * dy + dz * dz;
            }
            {
                float dx = va.w - wa.w, dy = vb.x - wb.x, dz = vb.y - wb.y;
                s2[1] = dx * dx + dy * dy + dz * dz;
            }
            {
                float dx = vb.z - wb.z, dy = vb.w - wb.w, dz = vc.x - wc.x;
                s2[2] = dx * dx + dy * dy + dz * dz;
            }
            {
                float dx = vc.y - wc.y, dy = vc.z - wc.z, dz = vc.w - wc.w;
                s2[3] = dx * dx + dy * dy + dz * dz;
            }

            float prod = 1.0f;
#pragma unroll
            for (int k = 0; k < 4; ++k) {
                const float s     = s2[k];
                const bool  close = s < ts;
                const float phit  = c * __expf(nli * s);
                const float p     = phit + omh;
                prod *= close ? p : 1.0f;
                const float post = __fdividef(phit, p);
                shit += (close && phit > t19) ? post : 0.0f;
            }
            slog += __logf(prod);
        }

        mbar_arrive(mb + 16 * si + 8);         // arrive empty

        if (tid == 0 && i + NSTG < nloc) {
            mbar_wait(mb + 16 * si + 8, (i >> 2) & 1);
            const size_t off  = (size_t)(gs + NSTG) * STAGE_BYTES;
            const uint32_t bo = smem_base + si * BUF_BYTES;
            mbar_expect_tx(mb + 16 * si, 2 * STAGE_BYTES);
            bulk_ld_pol(bo,               gp + off, STAGE_BYTES, mb + 16 * si, POL_P);
            bulk_ld_pol(bo + STAGE_BYTES, go + off, STAGE_BYTES, mb + 16 * si, POL_O);
        }
    }

    // final flush
#pragma unroll
    for (int off = 16; off > 0; off >>= 1) {
        slog += __shfl_down_sync(0xFFFFFFFFu, slog, off);
        shit += __shfl_down_sync(0xFFFFFFFFu, shit, off);
    }
    if (lane == 0) { sl[wid] = slog; sh[wid] = shit; }
    __syncthreads();
    if (tid == 0) {
        float ta = 0.0f, tb = 0.0f;
#pragma unroll
        for (int w = 0; w < THREADS / 32; ++w) { ta += sl[w]; tb += sh[w]; }
        atomicAdd(&g_acc[cur_seg], ta);
        atomicAdd(&g_acc[SEGS + cur_seg], tb);
    }

    // completion ticket: last block writes output + resets state (graph-replay safe)
    __threadfence();
    if (tid == 0) s_ticket = atomicAdd(&g_done, 1u);
    __syncthreads();
    if (s_ticket == NBLK - 1) {
        __threadfence();
        if (tid < SEGS) {
            const float lv = g_acc[tid];
            const float hv = g_acc[SEGS + tid];
            out[tid]            = lv;
            out[SEGS + tid]     = hv;
            out[2 * SEGS + tid] = hv;
            g_acc[tid]        = 0.0f;
            g_acc[SEGS + tid] = 0.0f;
        }
        if (tid == 0) g_done = 0u;
    }
}

extern "C" void kernel_launch(void* const* d_in, const int* in_sizes, int n_in,
                              void* d_out, int out_size) {
    const float* u_pred = (const float*)d_in[0];
    const float* u_obs  = (const float*)d_in[1];
    const float* h      = (const float*)d_in[2];
    const float* lam    = (const float*)d_in[3];
    const float* thresh = (const float*)d_in[4];
    float* out = (float*)d_out;

    cudaFuncSetAttribute(trajectory_score_kernel,
                         cudaFuncAttributeMaxDynamicSharedMemorySize, SMEM_TOTAL);
    trajectory_score_kernel<<<NBLK, THREADS, SMEM_TOTAL>>>(
        u_pred, u_obs, h, lam, thresh, out);
}

// round 8
// speedup vs baseline: 1.1260x; 1.1260x over previous
#include <cuda_runtime.h>
#include <cstdint>

// TrajectoryScore: 64 segments x 100000 obs. HBM-streaming reduction.
// out[0:64)=log_like, out[64:128)=hits, out[128:192)=hits_raw(==hits).
//
// R7: R5's TMA pipeline + L2 pinning. u_pred (76.8MB) evict_last; u_obs
// pinned DETERMINISTICALLY by address range: first 2600 stages (31.2MB)
// evict_last, rest evict_first. Total pinned 108MB < 126MB L2, and the
// pinned line set is identical across graph replays (stable residency,
// unlike R6's per-access fractional randomization).

#define SEGS        64
#define SPS         100                 // stages per segment
#define NSTAGE      (SEGS * SPS)        // 6400
#define STAGE_BYTES 12000               // per tensor (1000 rows), 16B multiple
#define GROUPS      250                 // 4-row groups per stage
#define THREADS     256
#define NBLK        296                 // 148 SMs * 2 CTAs
#define QW          (NSTAGE / NBLK)     // 21
#define RW          (NSTAGE - NBLK * QW)// 184
#define NSTG        4                   // pipeline depth
#define BUF_BYTES   (2 * STAGE_BYTES)   // pred + obs per stage (24000)
#define MBAR_OFF    (NSTG * BUF_BYTES)  // 96000
#define SMEM_TOTAL  (MBAR_OFF + 2 * NSTG * 8)
#define PIN_STG_O   2600                // u_obs stages pinned (31.2MB)

__device__ float        g_acc[2 * SEGS];   // zero-init at module load
__device__ unsigned int g_done;

__device__ __forceinline__ uint32_t smem_u32(const void* p) {
    uint32_t r;
    asm("{ .reg .u64 t; cvta.to.shared.u64 t, %1; cvt.u32.u64 %0, t; }"
        : "=r"(r) : "l"(p));
    return r;
}
__device__ __forceinline__ void mbar_init(uint32_t a, uint32_t cnt) {
    asm volatile("mbarrier.init.shared.b64 [%0], %1;" :: "r"(a), "r"(cnt) : "memory");
}
__device__ __forceinline__ void mbar_arrive(uint32_t a) {
    asm volatile("mbarrier.arrive.shared.b64 _, [%0];" :: "r"(a) : "memory");
}
__device__ __forceinline__ void mbar_expect_tx(uint32_t a, uint32_t bytes) {
    asm volatile("mbarrier.arrive.expect_tx.shared.b64 _, [%0], %1;"
                 :: "r"(a), "r"(bytes) : "memory");
}
__device__ __forceinline__ void mbar_wait(uint32_t a, uint32_t phase) {
    asm volatile(
        "{\n\t.reg .pred P;\n\t"
        "W%=:\n\t"
        "mbarrier.try_wait.parity.acquire.cta.shared::cta.b64 P, [%0], %1, 0x989680;\n\t"
        "@P bra D%=;\n\t"
        "bra W%=;\n\t"
        "D%=:\n\t}"
        :: "r"(a), "r"(phase) : "memory");
}
// TMA bulk load with explicit L2 eviction policy
__device__ __forceinline__ void bulk_ld_pol(uint32_t smem_dst, const void* gsrc,
                                            uint32_t bytes, uint32_t mbar,
                                            uint64_t pol) {
    asm volatile(
        "cp.async.bulk.shared::cta.global.mbarrier::complete_tx::bytes.L2::cache_hint "
        "[%0], [%1], %2, [%3], %4;"
        :: "r"(smem_dst), "l"(gsrc), "r"(bytes), "r"(mbar), "l"(pol) : "memory");
}
__device__ __forceinline__ uint64_t pol_evict_last() {
    uint64_t p;
    asm("createpolicy.fractional.L2::evict_last.b64 %0, 1.0;" : "=l"(p));
    return p;
}
__device__ __forceinline__ uint64_t pol_evict_first() {
    uint64_t p;
    asm("createpolicy.fractional.L2::evict_first.b64 %0, 1.0;" : "=l"(p));
    return p;
}

__global__ __launch_bounds__(THREADS, 2)
void trajectory_score_kernel(const float* __restrict__ u_pred,
                             const float* __restrict__ u_obs,
                             const float* __restrict__ h,
                             const float* __restrict__ lam,
                             const float* __restrict__ thresh,
                             float* __restrict__ out) {
    extern __shared__ char dsm[];
    const int b   = blockIdx.x;
    const int tid = threadIdx.x;

    const uint32_t smem_base = smem_u32(dsm);
    const uint32_t mb        = smem_base + MBAR_OFF;   // full[i]@+16i, empty@+16i+8

    __shared__ float    sl[THREADS / 32];
    __shared__ float    sh[THREADS / 32];
    __shared__ unsigned s_ticket;

    const int s0   = b * QW + min(b, RW);
    const int nloc = QW + (b < RW ? 1 : 0);

    const char* gp = (const char*)u_pred;
    const char* go = (const char*)u_obs;

    if (tid == 0) {
#pragma unroll
        for (int i = 0; i < NSTG; ++i) {
            mbar_init(mb + 16 * i, 1);           // full
            mbar_init(mb + 16 * i + 8, THREADS); // empty
        }
    }
    __syncthreads();

    const uint64_t POL_EL = pol_evict_last();    // pinned lines
    const uint64_t POL_EF = pol_evict_first();   // streaming lines

    if (tid == 0) {
        asm volatile("fence.proxy.async.shared::cta;" ::: "memory");
        const int pre = min(NSTG, nloc);
        for (int j = 0; j < pre; ++j) {
            const int    st   = s0 + j;
            const size_t off  = (size_t)st * STAGE_BYTES;
            const uint32_t bo = smem_base + j * BUF_BYTES;
            mbar_expect_tx(mb + 16 * j, 2 * STAGE_BYTES);
            bulk_ld_pol(bo,               gp + off, STAGE_BYTES, mb + 16 * j, POL_EL);
            bulk_ld_pol(bo + STAGE_BYTES, go + off, STAGE_BYTES, mb + 16 * j,
                        (st < PIN_STG_O) ? POL_EL : POL_EF);
        }
    }

    const int lane = tid & 31;
    const int wid  = tid >> 5;

    float slog = 0.0f, shit = 0.0f;
    int   cur_seg = s0 / SPS;

    float hs  = __ldg(h + cur_seg);
    float ls  = __ldg(lam + cur_seg);
    float ts  = __ldg(thresh + cur_seg);
    float c   = hs * ls * __frcp_rn(1.0f - __expf(-ls));
    float omh = 1.0f - hs;
    float nli = -ls * __frcp_rn(ts);
    float t19 = 19.0f * omh;

    for (int i = 0; i < nloc; ++i) {
        const int gs  = s0 + i;
        const int seg = gs / SPS;
        if (seg != cur_seg) {
#pragma unroll
            for (int off = 16; off > 0; off >>= 1) {
                slog += __shfl_down_sync(0xFFFFFFFFu, slog, off);
                shit += __shfl_down_sync(0xFFFFFFFFu, shit, off);
            }
            if (lane == 0) { sl[wid] = slog; sh[wid] = shit; }
            __syncthreads();
            if (tid == 0) {
                float ta = 0.0f, tb = 0.0f;
#pragma unroll
                for (int w = 0; w < THREADS / 32; ++w) { ta += sl[w]; tb += sh[w]; }
                atomicAdd(&g_acc[cur_seg], ta);
                atomicAdd(&g_acc[SEGS + cur_seg], tb);
            }
            __syncthreads();
            slog = 0.0f; shit = 0.0f;
            cur_seg = seg;
            hs  = __ldg(h + seg);
            ls  = __ldg(lam + seg);
            ts  = __ldg(thresh + seg);
            c   = hs * ls * __frcp_rn(1.0f - __expf(-ls));
            omh = 1.0f - hs;
            nli = -ls * __frcp_rn(ts);
            t19 = 19.0f * omh;
        }

        const int      si = i & (NSTG - 1);
        const uint32_t ph = (i >> 2) & 1;
        mbar_wait(mb + 16 * si, ph);           // wait full

        if (tid < GROUPS) {
            const char* pb = dsm + si * BUF_BYTES + 48 * tid;
            const float4 va = *(const float4*)(pb + 0);
            const float4 vb = *(const float4*)(pb + 16);
            const float4 vc = *(const float4*)(pb + 32);
            const float4 wa = *(const float4*)(pb + STAGE_BYTES + 0);
            const float4 wb = *(const float4*)(pb + STAGE_BYTES + 16);
            const float4 wc = *(const float4*)(pb + STAGE_BYTES + 32);

            float s2[4];
            {
                float dx = va.x - wa.x, dy = va.y - wa.y, dz = va.z - wa.z;
                s2[0] = dx * dx + dy * dy + dz * dz;
            }
            {
                float dx = va.w - wa.w, dy = vb.x - wb.x, dz = vb.y - wb.y;
                s2[1] = dx * dx + dy * dy + dz * dz;
            }
            {
                float dx = vb.z - wb.z, dy = vb.w - wb.w, dz = vc.x - wc.x;
                s2[2] = dx * dx + dy * dy + dz * dz;
            }
            {
                float dx = vc.y - wc.y, dy = vc.z - wc.z, dz = vc.w - wc.w;
                s2[3] = dx * dx + dy * dy + dz * dz;
            }

            float prod = 1.0f;
#pragma unroll
            for (int k = 0; k < 4; ++k) {
                const float s     = s2[k];
                const bool  close = s < ts;
                const float phit  = c * __expf(nli * s);
                const float p     = phit + omh;
                prod *= close ? p : 1.0f;
                const float post = __fdividef(phit, p);
                shit += (close && phit > t19) ? post : 0.0f;
            }
            slog += __logf(prod);
        }

        mbar_arrive(mb + 16 * si + 8);         // arrive empty

        if (tid == 0 && i + NSTG < nloc) {
            mbar_wait(mb + 16 * si + 8, (i >> 2) & 1);
            const int    st   = gs + NSTG;
            const size_t off  = (size_t)st * STAGE_BYTES;
            const uint32_t bo = smem_base + si * BUF_BYTES;
            mbar_expect_tx(mb + 16 * si, 2 * STAGE_BYTES);
            bulk_ld_pol(bo,               gp + off, STAGE_BYTES, mb + 16 * si, POL_EL);
            bulk_ld_pol(bo + STAGE_BYTES, go + off, STAGE_BYTES, mb + 16 * si,
                        (st < PIN_STG_O) ? POL_EL : POL_EF);
        }
    }

    // final flush
#pragma unroll
    for (int off = 16; off > 0; off >>= 1) {
        slog += __shfl_down_sync(0xFFFFFFFFu, slog, off);
        shit += __shfl_down_sync(0xFFFFFFFFu, shit, off);
    }
    if (lane == 0) { sl[wid] = slog; sh[wid] = shit; }
    __syncthreads();
    if (tid == 0) {
        float ta = 0.0f, tb = 0.0f;
#pragma unroll
        for (int w = 0; w < THREADS / 32; ++w) { ta += sl[w]; tb += sh[w]; }
        atomicAdd(&g_acc[cur_seg], ta);
        atomicAdd(&g_acc[SEGS + cur_seg], tb);
    }

    // completion ticket: last block writes output + resets state (graph-replay safe)
    __threadfence();
    if (tid == 0) s_ticket = atomicAdd(&g_done, 1u);
    __syncthreads();
    if (s_ticket == NBLK - 1) {
        __threadfence();
        if (tid < SEGS) {
            const float lv = g_acc[tid];
            const float hv = g_acc[SEGS + tid];
            out[tid]            = lv;
            out[SEGS + tid]     = hv;
            out[2 * SEGS + tid] = hv;
            g_acc[tid]        = 0.0f;
            g_acc[SEGS + tid] = 0.0f;
        }
        if (tid == 0) g_done = 0u;
    }
}

extern "C" void kernel_launch(void* const* d_in, const int* in_sizes, int n_in,
                              void* d_out, int out_size) {
    const float* u_pred = (const float*)d_in[0];
    const float* u_obs  = (const float*)d_in[1];
    const float* h      = (const float*)d_in[2];
    const float* lam    = (const float*)d_in[3];
    const float* thresh = (const float*)d_in[4];
    float* out = (float*)d_out;

    cudaFuncSetAttribute(trajectory_score_kernel,
                         cudaFuncAttributeMaxDynamicSharedMemorySize, SMEM_TOTAL);
    trajectory_score_kernel<<<NBLK, THREADS, SMEM_TOTAL>>>(
        u_pred, u_obs, h, lam, thresh, out);
}

// round 9
// speedup vs baseline: 1.5055x; 1.3370x over previous
#include <cuda_runtime.h>
#include <cstdint>

// TrajectoryScore: 64 segments x 100000 obs. HBM-streaming reduction.
// out[0:64)=log_like, out[64:128)=hits, out[128:192)=hits_raw(==hits).
//
// R8: R5 (TMA pipeline + u_pred-only L2 evict_last pin = best known) plus a
// DEDICATED PRODUCER WARP. 288 threads: warps 0-7 consume (250 active),
// warp 8's elected thread issues all cp.async.bulk loads in its own loop.
// Removes the R5 critical path where tid0 computed a full stage before
// issuing each refill. Consumer flushes use named bar.sync 1,256 so the
// producer warp never joins mid-loop barriers.

#define SEGS        64
#define SPS         100                 // stages per segment
#define NSTAGE      (SEGS * SPS)        // 6400
#define STAGE_BYTES 12000               // per tensor (1000 rows), 16B multiple
#define GROUPS      250                 // 4-row groups per stage
#define CONS        256                 // consumer threads (warps 0-7)
#define THREADS     288                 // + producer warp 8
#define NBLK        296                 // 148 SMs * 2 CTAs
#define QW          (NSTAGE / NBLK)     // 21
#define RW          (NSTAGE - NBLK * QW)// 184
#define NSTG        4                   // pipeline depth
#define BUF_BYTES   (2 * STAGE_BYTES)   // pred + obs per stage (24000)
#define MBAR_OFF    (NSTG * BUF_BYTES)  // 96000
#define SMEM_TOTAL  (MBAR_OFF + 2 * NSTG * 8)

__device__ float        g_acc[2 * SEGS];   // zero-init at module load
__device__ unsigned int g_done;

__device__ __forceinline__ uint32_t smem_u32(const void* p) {
    uint32_t r;
    asm("{ .reg .u64 t; cvta.to.shared.u64 t, %1; cvt.u32.u64 %0, t; }"
        : "=r"(r) : "l"(p));
    return r;
}
__device__ __forceinline__ void mbar_init(uint32_t a, uint32_t cnt) {
    asm volatile("mbarrier.init.shared.b64 [%0], %1;" :: "r"(a), "r"(cnt) : "memory");
}
__device__ __forceinline__ void mbar_arrive(uint32_t a) {
    asm volatile("mbarrier.arrive.shared.b64 _, [%0];" :: "r"(a) : "memory");
}
__device__ __forceinline__ void mbar_expect_tx(uint32_t a, uint32_t bytes) {
    asm volatile("mbarrier.arrive.expect_tx.shared.b64 _, [%0], %1;"
                 :: "r"(a), "r"(bytes) : "memory");
}
__device__ __forceinline__ void mbar_wait(uint32_t a, uint32_t phase) {
    asm volatile(
        "{\n\t.reg .pred P;\n\t"
        "W%=:\n\t"
        "mbarrier.try_wait.parity.acquire.cta.shared::cta.b64 P, [%0], %1, 0x989680;\n\t"
        "@P bra D%=;\n\t"
        "bra W%=;\n\t"
        "D%=:\n\t}"
        :: "r"(a), "r"(phase) : "memory");
}
__device__ __forceinline__ void bulk_ld_pol(uint32_t smem_dst, const void* gsrc,
                                            uint32_t bytes, uint32_t mbar,
                                            uint64_t pol) {
    asm volatile(
        "cp.async.bulk.shared::cta.global.mbarrier::complete_tx::bytes.L2::cache_hint "
        "[%0], [%1], %2, [%3], %4;"
        :: "r"(smem_dst), "l"(gsrc), "r"(bytes), "r"(mbar), "l"(pol) : "memory");
}
__device__ __forceinline__ uint64_t pol_evict_last() {
    uint64_t p;
    asm("createpolicy.fractional.L2::evict_last.b64 %0, 1.0;" : "=l"(p));
    return p;
}
__device__ __forceinline__ uint64_t pol_evict_first() {
    uint64_t p;
    asm("createpolicy.fractional.L2::evict_first.b64 %0, 1.0;" : "=l"(p));
    return p;
}
__device__ __forceinline__ uint32_t elect_one() {
    uint32_t pred;
    asm volatile(
        "{\n\t.reg .pred p;\n\t"
        "elect.sync _|p, 0xFFFFFFFF;\n\t"
        "selp.b32 %0, 1, 0, p;\n\t}"
        : "=r"(pred));
    return pred;
}

__global__ __launch_bounds__(THREADS, 2)
void trajectory_score_kernel(const float* __restrict__ u_pred,
                             const float* __restrict__ u_obs,
                             const float* __restrict__ h,
                             const float* __restrict__ lam,
                             const float* __restrict__ thresh,
                             float* __restrict__ out) {
    extern __shared__ char dsm[];
    const int b   = blockIdx.x;
    const int tid = threadIdx.x;
    const int wid = tid >> 5;

    const uint32_t smem_base = smem_u32(dsm);
    const uint32_t mb        = smem_base + MBAR_OFF;   // full[i]@+16i, empty@+16i+8

    __shared__ float    sl[CONS / 32];
    __shared__ float    sh[CONS / 32];
    __shared__ unsigned s_ticket;

    const int s0   = b * QW + min(b, RW);
    const int nloc = QW + (b < RW ? 1 : 0);

    if (tid == 0) {
#pragma unroll
        for (int i = 0; i < NSTG; ++i) {
            mbar_init(mb + 16 * i, 1);        // full: producer expect_tx
            mbar_init(mb + 16 * i + 8, CONS); // empty: all consumers arrive
        }
    }
    __syncthreads();

    if (wid == 8) {
        // ---------------- producer warp ----------------
        if (elect_one()) {
            const uint64_t POL_P = pol_evict_last();   // u_pred pinned in L2
            const uint64_t POL_O = pol_evict_first();  // u_obs streams
            const char* gp = (const char*)u_pred;
            const char* go = (const char*)u_obs;
            asm volatile("fence.proxy.async.shared::cta;" ::: "memory");
            for (int i = 0; i < nloc; ++i) {
                const int si = i & (NSTG - 1);
                if (i >= NSTG)
                    mbar_wait(mb + 16 * si + 8, ((i >> 2) + 1) & 1);
                const size_t off  = (size_t)(s0 + i) * STAGE_BYTES;
                const uint32_t bo = smem_base + si * BUF_BYTES;
                mbar_expect_tx(mb + 16 * si, 2 * STAGE_BYTES);
                bulk_ld_pol(bo,               gp + off, STAGE_BYTES, mb + 16 * si, POL_P);
                bulk_ld_pol(bo + STAGE_BYTES, go + off, STAGE_BYTES, mb + 16 * si, POL_O);
            }
        }
    } else {
        // ---------------- consumer warps 0-7 ----------------
        const int lane = tid & 31;

        float slog = 0.0f, shit = 0.0f;
        int   cur_seg = s0 / SPS;

        float hs  = __ldg(h + cur_seg);
        float ls  = __ldg(lam + cur_seg);
        float ts  = __ldg(thresh + cur_seg);
        float c   = hs * ls * __frcp_rn(1.0f - __expf(-ls));
        float omh = 1.0f - hs;
        float nli = -ls * __frcp_rn(ts);
        float t19 = 19.0f * omh;

        for (int i = 0; i < nloc; ++i) {
            const int seg = (s0 + i) / SPS;
            if (seg != cur_seg) {
                // flush block partials for cur_seg (consumers only)
#pragma unroll
                for (int off = 16; off > 0; off >>= 1) {
                    slog += __shfl_down_sync(0xFFFFFFFFu, slog, off);
                    shit += __shfl_down_sync(0xFFFFFFFFu, shit, off);
                }
                if (lane == 0) { sl[wid] = slog; sh[wid] = shit; }
                asm volatile("bar.sync 1, %0;" :: "r"(CONS) : "memory");
                if (tid == 0) {
                    float ta = 0.0f, tb = 0.0f;
#pragma unroll
                    for (int w = 0; w < CONS / 32; ++w) { ta += sl[w]; tb += sh[w]; }
                    atomicAdd(&g_acc[cur_seg], ta);
                    atomicAdd(&g_acc[SEGS + cur_seg], tb);
                }
                asm volatile("bar.sync 1, %0;" :: "r"(CONS) : "memory");
                slog = 0.0f; shit = 0.0f;
                cur_seg = seg;
                hs  = __ldg(h + seg);
                ls  = __ldg(lam + seg);
                ts  = __ldg(thresh + seg);
                c   = hs * ls * __frcp_rn(1.0f - __expf(-ls));
                omh = 1.0f - hs;
                nli = -ls * __frcp_rn(ts);
                t19 = 19.0f * omh;
            }

            const int      si = i & (NSTG - 1);
            const uint32_t ph = (i >> 2) & 1;
            mbar_wait(mb + 16 * si, ph);           // wait full

            if (tid < GROUPS) {
                const char* pb = dsm + si * BUF_BYTES + 48 * tid;
                const float4 va = *(const float4*)(pb + 0);
                const float4 vb = *(const float4*)(pb + 16);
                const float4 vc = *(const float4*)(pb + 32);
                const float4 wa = *(const float4*)(pb + STAGE_BYTES + 0);
                const float4 wb = *(const float4*)(pb + STAGE_BYTES + 16);
                const float4 wc = *(const float4*)(pb + STAGE_BYTES + 32);

                float s2[4];
                {
                    float dx = va.x - wa.x, dy = va.y - wa.y, dz = va.z - wa.z;
                    s2[0] = dx * dx + dy * dy + dz * dz;
                }
                {
                    float dx = va.w - wa.w, dy = vb.x - wb.x, dz = vb.y - wb.y;
                    s2[1] = dx * dx + dy * dy + dz * dz;
                }
                {
                    float dx = vb.z - wb.z, dy = vb.w - wb.w, dz = vc.x - wc.x;
                    s2[2] = dx * dx + dy * dy + dz * dz;
                }
                {
                    float dx = vc.y - wc.y, dy = vc.z - wc.z, dz = vc.w - wc.w;
                    s2[3] = dx * dx + dy * dy + dz * dz;
                }

                float prod = 1.0f;
#pragma unroll
                for (int k = 0; k < 4; ++k) {
                    const float s     = s2[k];
                    const bool  close = s < ts;
                    const float phit  = c * __expf(nli * s);
                    const float p     = phit + omh;
                    prod *= close ? p : 1.0f;
                    const float post = __fdividef(phit, p);
                    shit += (close && phit > t19) ? post : 0.0f;
                }
                slog += __logf(prod);
            }

            mbar_arrive(mb + 16 * si + 8);         // arrive empty
        }

        // final flush (consumers only)
#pragma unroll
        for (int off = 16; off > 0; off >>= 1) {
            slog += __shfl_down_sync(0xFFFFFFFFu, slog, off);
            shit += __shfl_down_sync(0xFFFFFFFFu, shit, off);
        }
        if (lane == 0) { sl[wid] = slog; sh[wid] = shit; }
        asm volatile("bar.sync 1, %0;" :: "r"(CONS) : "memory");
        if (tid == 0) {
            float ta = 0.0f, tb = 0.0f;
#pragma unroll
            for (int w = 0; w < CONS / 32; ++w) { ta += sl[w]; tb += sh[w]; }
            atomicAdd(&g_acc[cur_seg], ta);
            atomicAdd(&g_acc[SEGS + cur_seg], tb);
        }
    }

    // all 288 threads converge here
    __syncthreads();

    // completion ticket: last block writes output + resets state (graph-replay safe)
    __threadfence();
    if (tid == 0) s_ticket = atomicAdd(&g_done, 1u);
    __syncthreads();
    if (s_ticket == NBLK - 1) {
        __threadfence();
        if (tid < SEGS) {
            const float lv = g_acc[tid];
            const float hv = g_acc[SEGS + tid];
            out[tid]            = lv;
            out[SEGS + tid]     = hv;
            out[2 * SEGS + tid] = hv;
            g_acc[tid]        = 0.0f;
            g_acc[SEGS + tid] = 0.0f;
        }
        if (tid == 0) g_done = 0u;
    }
}

extern "C" void kernel_launch(void* const* d_in, const int* in_sizes, int n_in,
                              void* d_out, int out_size) {
    const float* u_pred = (const float*)d_in[0];
    const float* u_obs  = (const float*)d_in[1];
    const float* h      = (const float*)d_in[2];
    const float* lam    = (const float*)d_in[3];
    const float* thresh = (const float*)d_in[4];
    float* out = (float*)d_out;

    cudaFuncSetAttribute(trajectory_score_kernel,
                         cudaFuncAttributeMaxDynamicSharedMemorySize, SMEM_TOTAL);
    trajectory_score_kernel<<<NBLK, THREADS, SMEM_TOTAL>>>(
        u_pred, u_obs, h, lam, thresh, out);
}